// round 1
// baseline (speedup 1.0000x reference)
#include <cuda_runtime.h>
#include <math.h>

#define NTOK 8192
#define EDIM 512
#define SEQ  2048
#define NB   4
#define HEADS 8
#define HD   64
#define FFDIM 2048
#define NLAYER 2

// ---------------- scratch (device globals; no allocation) ----------------
__device__ float g_h[NTOK * EDIM];
__device__ float g_q[NTOK * EDIM];
__device__ float g_k[NTOK * EDIM];
__device__ float g_v[NTOK * EDIM];
__device__ float g_a[NTOK * EDIM];
__device__ float g_p[NTOK * EDIM];
__device__ float g_f[NTOK * FFDIM];

// ---------------- embedding + positional ----------------
__global__ void embed_kernel(const int* __restrict__ x,
                             const float* __restrict__ emb,
                             const float* __restrict__ pos,
                             float* __restrict__ h) {
    int idx = blockIdx.x * blockDim.x + threadIdx.x;   // over NTOK*EDIM
    int n = idx >> 9;          // / 512
    int e = idx & 511;
    int tok = x[n] + 1;
    int s = n & (SEQ - 1);
    h[idx] = emb[tok * EDIM + e] + pos[s * EDIM + e];
}

// ---------------- tiled SGEMM: C[N,M] = A[N,K] @ W[K,M] + bias (opt ReLU) --
// BM=BN=64, BK=32, 256 threads, 4x4 micro-tile per thread.
template <bool RELU>
__global__ __launch_bounds__(256)
void gemm_kernel(const float* __restrict__ A, const float* __restrict__ W,
                 const float* __restrict__ bias, float* __restrict__ C,
                 int K, int M) {
    __shared__ float As[32][68];   // As[k][m] (transposed)
    __shared__ float Bs[32][68];   // Bs[k][n]

    int tid = threadIdx.x;
    int tx = tid & 15, ty = tid >> 4;
    int rowBase = blockIdx.y * 64;
    int colBase = blockIdx.x * 64;

    float acc[4][4] = {};

    for (int k0 = 0; k0 < K; k0 += 32) {
        // load A tile 64x32 (2 float4 per thread), store transposed
        #pragma unroll
        for (int i = 0; i < 2; i++) {
            int f = tid + i * 256;        // 0..511
            int r = f >> 3;               // row 0..63
            int c4 = (f & 7) * 4;         // kcol 0..28
            float4 a = *(const float4*)(A + (size_t)(rowBase + r) * K + k0 + c4);
            As[c4 + 0][r] = a.x;
            As[c4 + 1][r] = a.y;
            As[c4 + 2][r] = a.z;
            As[c4 + 3][r] = a.w;
        }
        // load B tile 32x64 (2 float4 per thread)
        #pragma unroll
        for (int i = 0; i < 2; i++) {
            int f = tid + i * 256;
            int r = f >> 4;               // 0..31
            int c4 = (f & 15) * 4;        // 0..60
            *(float4*)&Bs[r][c4] = *(const float4*)(W + (size_t)(k0 + r) * M + colBase + c4);
        }
        __syncthreads();

        #pragma unroll
        for (int kk = 0; kk < 32; kk++) {
            float4 a = *(const float4*)&As[kk][ty * 4];
            float4 b = *(const float4*)&Bs[kk][tx * 4];
            float av[4] = {a.x, a.y, a.z, a.w};
            float bv[4] = {b.x, b.y, b.z, b.w};
            #pragma unroll
            for (int i = 0; i < 4; i++)
                #pragma unroll
                for (int j = 0; j < 4; j++)
                    acc[i][j] = fmaf(av[i], bv[j], acc[i][j]);
        }
        __syncthreads();
    }

    float4 bs = *(const float4*)(bias + colBase + tx * 4);
    float bb[4] = {bs.x, bs.y, bs.z, bs.w};
    #pragma unroll
    for (int i = 0; i < 4; i++) {
        int r = rowBase + ty * 4 + i;
        float4 o;
        float v0 = acc[i][0] + bb[0];
        float v1 = acc[i][1] + bb[1];
        float v2 = acc[i][2] + bb[2];
        float v3 = acc[i][3] + bb[3];
        if (RELU) {
            v0 = fmaxf(v0, 0.f); v1 = fmaxf(v1, 0.f);
            v2 = fmaxf(v2, 0.f); v3 = fmaxf(v3, 0.f);
        }
        o.x = v0; o.y = v1; o.z = v2; o.w = v3;
        *(float4*)(C + (size_t)r * M + colBase + tx * 4) = o;
    }
}

// ---------------- flash-style attention ----------------
// grid: (SEQ/64, B*HEADS), 256 threads. 64-query tile, stream 64-key blocks.
// smem: Qts[d][q], Kts[d][k], Vs[k][d], Pts[k][q], all stride 68.
#define ASTR 68
__global__ __launch_bounds__(256)
void attn_kernel(const float* __restrict__ Q, const float* __restrict__ Kk,
                 const float* __restrict__ Vv, const int* __restrict__ mask,
                 float* __restrict__ O) {
    extern __shared__ float sm[];
    float* Qts = sm;
    float* Kts = sm + 64 * ASTR;
    float* Vs  = sm + 2 * 64 * ASTR;
    float* Pts = sm + 3 * 64 * ASTR;

    int tid = threadIdx.x;
    int tx = tid & 15, ty = tid >> 4;
    int bh = blockIdx.y;
    int b  = bh >> 3;      // / HEADS
    int hh = bh & 7;
    int q0 = blockIdx.x * 64;
    const float scale = 0.125f;

    // load Q tile (64 q x 64 d), transposed into Qts[d][q]
    #pragma unroll
    for (int i = 0; i < 4; i++) {
        int f4 = tid + i * 256;              // 0..1023
        int q  = f4 >> 4;                    // 0..63
        int d4 = (f4 & 15) * 4;
        float4 a = *(const float4*)(Q + (size_t)(b * SEQ + q0 + q) * EDIM + hh * HD + d4);
        Qts[(d4 + 0) * ASTR + q] = a.x;
        Qts[(d4 + 1) * ASTR + q] = a.y;
        Qts[(d4 + 2) * ASTR + q] = a.z;
        Qts[(d4 + 3) * ASTR + q] = a.w;
    }

    float accO[4][4] = {};
    float mrun[4] = {-1e30f, -1e30f, -1e30f, -1e30f};
    float lrun[4] = {0.f, 0.f, 0.f, 0.f};

    __syncthreads();

    for (int k0 = 0; k0 < SEQ; k0 += 64) {
        // load K (transposed) and V (natural)
        #pragma unroll
        for (int i = 0; i < 4; i++) {
            int f4 = tid + i * 256;
            int k  = f4 >> 4;
            int d4 = (f4 & 15) * 4;
            float4 a = *(const float4*)(Kk + (size_t)(b * SEQ + k0 + k) * EDIM + hh * HD + d4);
            Kts[(d4 + 0) * ASTR + k] = a.x;
            Kts[(d4 + 1) * ASTR + k] = a.y;
            Kts[(d4 + 2) * ASTR + k] = a.z;
            Kts[(d4 + 3) * ASTR + k] = a.w;
            float4 v = *(const float4*)(Vv + (size_t)(b * SEQ + k0 + k) * EDIM + hh * HD + d4);
            *(float4*)&Vs[k * ASTR + d4] = v;
        }
        __syncthreads();

        // phase 1: scores s[q_i][k_j]
        float s[4][4] = {};
        #pragma unroll 8
        for (int d = 0; d < 64; d++) {
            float4 qa = *(const float4*)&Qts[d * ASTR + ty * 4];
            float4 kb = *(const float4*)&Kts[d * ASTR + tx * 4];
            float av[4] = {qa.x, qa.y, qa.z, qa.w};
            float bv[4] = {kb.x, kb.y, kb.z, kb.w};
            #pragma unroll
            for (int i = 0; i < 4; i++)
                #pragma unroll
                for (int j = 0; j < 4; j++)
                    s[i][j] = fmaf(av[i], bv[j], s[i][j]);
        }

        // mask + scale
        int4 mk = *(const int4*)(mask + b * SEQ + k0 + tx * 4);
        int mv[4] = {mk.x, mk.y, mk.z, mk.w};
        #pragma unroll
        for (int i = 0; i < 4; i++)
            #pragma unroll
            for (int j = 0; j < 4; j++)
                s[i][j] = (mv[j] == 0) ? -1e20f : s[i][j] * scale;

        // online softmax (per q-row; 16 lanes of a half-warp share a row group)
        #pragma unroll
        for (int i = 0; i < 4; i++) {
            float mloc = fmaxf(fmaxf(s[i][0], s[i][1]), fmaxf(s[i][2], s[i][3]));
            #pragma unroll
            for (int off = 8; off; off >>= 1)
                mloc = fmaxf(mloc, __shfl_xor_sync(0xffffffffu, mloc, off, 16));
            float mnew = fmaxf(mrun[i], mloc);
            float corr = __expf(mrun[i] - mnew);
            float psum = 0.f;
            #pragma unroll
            for (int j = 0; j < 4; j++) {
                float p = __expf(s[i][j] - mnew);
                Pts[(tx * 4 + j) * ASTR + ty * 4 + i] = p;
                psum += p;
            }
            #pragma unroll
            for (int off = 8; off; off >>= 1)
                psum += __shfl_xor_sync(0xffffffffu, psum, off, 16);
            lrun[i] = lrun[i] * corr + psum;
            mrun[i] = mnew;
            #pragma unroll
            for (int j = 0; j < 4; j++)
                accO[i][j] *= corr;
        }
        __syncthreads();

        // phase 2: accO[q_i][d_j] += P @ V
        #pragma unroll 8
        for (int kk = 0; kk < 64; kk++) {
            float4 pa = *(const float4*)&Pts[kk * ASTR + ty * 4];
            float4 vb = *(const float4*)&Vs[kk * ASTR + tx * 4];
            float av[4] = {pa.x, pa.y, pa.z, pa.w};
            float bv[4] = {vb.x, vb.y, vb.z, vb.w};
            #pragma unroll
            for (int i = 0; i < 4; i++)
                #pragma unroll
                for (int j = 0; j < 4; j++)
                    accO[i][j] = fmaf(av[i], bv[j], accO[i][j]);
        }
        __syncthreads();
    }

    // write output
    #pragma unroll
    for (int i = 0; i < 4; i++) {
        float inv = 1.f / lrun[i];
        float4 o = {accO[i][0] * inv, accO[i][1] * inv, accO[i][2] * inv, accO[i][3] * inv};
        *(float4*)(O + (size_t)(b * SEQ + q0 + ty * 4 + i) * EDIM + hh * HD + tx * 4) = o;
    }
}

// ---------------- residual + LayerNorm: out = LN(A + R) * g + be ----------
__global__ __launch_bounds__(128)
void ln_kernel(const float* __restrict__ A, const float* __restrict__ R,
               const float* __restrict__ g, const float* __restrict__ be,
               float* __restrict__ out) {
    __shared__ float red[4];
    int n = blockIdx.x;
    int t = threadIdx.x;           // 128 threads x 4 elems
    float4 a = ((const float4*)(A + (size_t)n * EDIM))[t];
    float4 r = ((const float4*)(R + (size_t)n * EDIM))[t];
    float v[4] = {a.x + r.x, a.y + r.y, a.z + r.z, a.w + r.w};

    float s = v[0] + v[1] + v[2] + v[3];
    #pragma unroll
    for (int o = 16; o; o >>= 1) s += __shfl_xor_sync(0xffffffffu, s, o);
    if ((t & 31) == 0) red[t >> 5] = s;
    __syncthreads();
    float mu = (red[0] + red[1] + red[2] + red[3]) * (1.f / EDIM);
    __syncthreads();

    v[0] -= mu; v[1] -= mu; v[2] -= mu; v[3] -= mu;
    float sq = v[0] * v[0] + v[1] * v[1] + v[2] * v[2] + v[3] * v[3];
    #pragma unroll
    for (int o = 16; o; o >>= 1) sq += __shfl_xor_sync(0xffffffffu, sq, o);
    if ((t & 31) == 0) red[t >> 5] = sq;
    __syncthreads();
    float var = (red[0] + red[1] + red[2] + red[3]) * (1.f / EDIM);
    float rs = rsqrtf(var + 1e-6f);

    float4 gg = ((const float4*)g)[t];
    float4 bb = ((const float4*)be)[t];
    float4 o;
    o.x = v[0] * rs * gg.x + bb.x;
    o.y = v[1] * rs * gg.y + bb.y;
    o.z = v[2] * rs * gg.z + bb.z;
    o.w = v[3] * rs * gg.w + bb.w;
    ((float4*)(out + (size_t)n * EDIM))[t] = o;
}

// ---------------- launcher ----------------
extern "C" void kernel_launch(void* const* d_in, const int* in_sizes, int n_in,
                              void* d_out, int out_size) {
    const int*   x    = (const int*)  d_in[0];
    const int*   mask = (const int*)  d_in[1];
    const float* emb  = (const float*)d_in[2];
    const float* pos  = (const float*)d_in[3];
    const float* Wq   = (const float*)d_in[4];
    const float* bq   = (const float*)d_in[5];
    const float* Wk   = (const float*)d_in[6];
    const float* bk   = (const float*)d_in[7];
    const float* Wv   = (const float*)d_in[8];
    const float* bv   = (const float*)d_in[9];
    const float* Wo   = (const float*)d_in[10];
    const float* bo   = (const float*)d_in[11];
    const float* g1   = (const float*)d_in[12];
    const float* be1  = (const float*)d_in[13];
    const float* g2   = (const float*)d_in[14];
    const float* be2  = (const float*)d_in[15];
    const float* W1   = (const float*)d_in[16];
    const float* bf1  = (const float*)d_in[17];
    const float* W2   = (const float*)d_in[18];
    const float* bf2  = (const float*)d_in[19];
    float* outp = (float*)d_out;

    float *h, *q, *k, *v, *a, *p, *f;
    cudaGetSymbolAddress((void**)&h, g_h);
    cudaGetSymbolAddress((void**)&q, g_q);
    cudaGetSymbolAddress((void**)&k, g_k);
    cudaGetSymbolAddress((void**)&v, g_v);
    cudaGetSymbolAddress((void**)&a, g_a);
    cudaGetSymbolAddress((void**)&p, g_p);
    cudaGetSymbolAddress((void**)&f, g_f);

    const int attn_smem = 4 * 64 * ASTR * sizeof(float);   // 69632
    cudaFuncSetAttribute(attn_kernel, cudaFuncAttributeMaxDynamicSharedMemorySize, attn_smem);

    embed_kernel<<<(NTOK * EDIM) / 256, 256>>>(x, emb, pos, h);

    dim3 gE(EDIM / 64, NTOK / 64);    // M=512
    dim3 gF(FFDIM / 64, NTOK / 64);   // M=2048

    for (int l = 0; l < NLAYER; l++) {
        const float* wq = Wq + (size_t)l * EDIM * EDIM;
        const float* wk = Wk + (size_t)l * EDIM * EDIM;
        const float* wv = Wv + (size_t)l * EDIM * EDIM;
        const float* wo = Wo + (size_t)l * EDIM * EDIM;
        const float* w1 = W1 + (size_t)l * EDIM * FFDIM;
        const float* w2 = W2 + (size_t)l * FFDIM * EDIM;

        gemm_kernel<false><<<gE, 256>>>(h, wq, bq + l * EDIM, q, EDIM, EDIM);
        gemm_kernel<false><<<gE, 256>>>(h, wk, bk + l * EDIM, k, EDIM, EDIM);
        gemm_kernel<false><<<gE, 256>>>(h, wv, bv + l * EDIM, v, EDIM, EDIM);

        attn_kernel<<<dim3(SEQ / 64, NB * HEADS), 256, attn_smem>>>(q, k, v, mask, a);

        gemm_kernel<false><<<gE, 256>>>(a, wo, bo + l * EDIM, p, EDIM, EDIM);
        ln_kernel<<<NTOK, 128>>>(p, h, g1 + l * EDIM, be1 + l * EDIM, h);

        gemm_kernel<true><<<gF, 256>>>(h, w1, bf1 + l * FFDIM, f, EDIM, FFDIM);
        gemm_kernel<false><<<gE, 256>>>(f, w2, bf2 + l * EDIM, p, FFDIM, EDIM);

        float* lnout = (l == NLAYER - 1) ? outp : h;
        ln_kernel<<<NTOK, 128>>>(p, h, g2 + l * EDIM, be2 + l * EDIM, lnout);
    }
}

// round 2
// speedup vs baseline: 1.3219x; 1.3219x over previous
#include <cuda_runtime.h>
#include <cuda_bf16.h>
#include <mma.h>
#include <math.h>

using namespace nvcuda;

#define NTOK 8192
#define EDIM 512
#define SEQ  2048
#define NB   4
#define HEADS 8
#define HD   64
#define FFDIM 2048
#define NLAYER 2

// ---------------- scratch (device globals; no allocation) ----------------
__device__ float g_h[NTOK * EDIM];
__device__ float g_q[NTOK * EDIM];
__device__ float g_k[NTOK * EDIM];
__device__ float g_v[NTOK * EDIM];
__device__ float g_a[NTOK * EDIM];
__device__ float g_p[NTOK * EDIM];
__device__ float g_f[NTOK * FFDIM];

// ---------------- embedding + positional ----------------
__global__ void embed_kernel(const int* __restrict__ x,
                             const float* __restrict__ emb,
                             const float* __restrict__ pos,
                             float* __restrict__ h) {
    int idx = blockIdx.x * blockDim.x + threadIdx.x;   // over NTOK*EDIM
    int n = idx >> 9;          // / 512
    int e = idx & 511;
    int tok = x[n] + 1;
    int s = n & (SEQ - 1);
    h[idx] = emb[tok * EDIM + e] + pos[s * EDIM + e];
}

// ---------------- bf16x3 tensor-core GEMM ----------------
// C[N,M] = A[N,K] @ W[K,M] + bias (opt ReLU), fp32 in/out.
// Split-precision: x = hi + lo (both bf16); A*B ~= Ah*Bh + Ah*Bl + Al*Bh.
// CTA tile 128x128x32, 256 threads (8 warps), warp tile 32x64 (2x4 wmma atoms).
#define BM 128
#define BN 128
#define BK 32
#define SA_STR 40      // A smem stride (elements), 80B = mult of 16B
#define SB_STR 136     // B smem stride (elements), 272B = mult of 16B
#define EPI_STR 68     // epilogue staging stride (floats)

// dynamic smem: main buffers 37,888B; epilogue staging 8*32*68*4 = 69,632B
#define GEMM_SMEM (8 * 32 * EPI_STR * 4)

template <bool RELU>
__global__ __launch_bounds__(256, 1)
void gemm_bf16x3_kernel(const float* __restrict__ A, const float* __restrict__ W,
                        const float* __restrict__ bias, float* __restrict__ C,
                        int K, int M) {
    extern __shared__ char dynsmem[];
    __nv_bfloat16* sAh = (__nv_bfloat16*)dynsmem;            // [BM][SA_STR]
    __nv_bfloat16* sAl = sAh + BM * SA_STR;
    __nv_bfloat16* sBh = sAl + BM * SA_STR;                  // [BK][SB_STR]
    __nv_bfloat16* sBl = sBh + BK * SB_STR;

    int tid = threadIdx.x;
    int lane = tid & 31;
    int wid = tid >> 5;
    int wm = wid & 3;            // 4 warps along M (32 rows each)
    int wn = wid >> 2;           // 2 warps along N (64 cols each)
    int rowBase = blockIdx.y * BM;
    int colBase = blockIdx.x * BN;

    wmma::fragment<wmma::accumulator, 16, 16, 16, float> acc[2][4];
    #pragma unroll
    for (int i = 0; i < 2; i++)
        #pragma unroll
        for (int j = 0; j < 4; j++)
            wmma::fill_fragment(acc[i][j], 0.0f);

    float4 ra[2], rb[2];
    // prefetch chunk 0
    #pragma unroll
    for (int i = 0; i < 2; i++) {
        int f = tid + i * 256;
        int r = f >> 3;                 // 0..127
        int c4 = (f & 7) << 2;          // 0..28
        ra[i] = *(const float4*)(A + (size_t)(rowBase + r) * K + c4);
        int rB = f >> 5;                // 0..31  (wait: f up to 511, rB up to 15) 
        (void)rB;
    }
    #pragma unroll
    for (int i = 0; i < 2; i++) {
        int f = tid + i * 256;
        int r = f >> 5;                 // 0..15 .. need 0..31 -> use 2 iters of 256 covering 512 float4s? 
        (void)r;
    }
    // NOTE: A tile = 128x32 floats = 1024 float4 -> 4 per thread.
    // B tile = 32x128 floats = 1024 float4 -> 4 per thread.
    // redo prefetch properly with 4 each:
    float4 pa[4], pb[4];
    #pragma unroll
    for (int i = 0; i < 4; i++) {
        int f = tid + i * 256;          // 0..1023
        int r = f >> 3;                 // 0..127
        int c4 = (f & 7) << 2;          // 0..28
        pa[i] = *(const float4*)(A + (size_t)(rowBase + r) * K + c4);
        int rB = f >> 5;                // 0..31
        int cB = (f & 31) << 2;         // 0..124
        pb[i] = *(const float4*)(W + (size_t)rB * M + colBase + cB);
    }

    for (int k0 = 0; k0 < K; k0 += BK) {
        // store current chunk (convert to hi/lo bf16)
        #pragma unroll
        for (int i = 0; i < 4; i++) {
            int f = tid + i * 256;
            int r = f >> 3;
            int c4 = (f & 7) << 2;
            float4 a = pa[i];
            __nv_bfloat16 hx = __float2bfloat16(a.x);
            __nv_bfloat16 hy = __float2bfloat16(a.y);
            __nv_bfloat16 hz = __float2bfloat16(a.z);
            __nv_bfloat16 hw = __float2bfloat16(a.w);
            __nv_bfloat16 lx = __float2bfloat16(a.x - __bfloat162float(hx));
            __nv_bfloat16 ly = __float2bfloat16(a.y - __bfloat162float(hy));
            __nv_bfloat16 lz = __float2bfloat16(a.z - __bfloat162float(hz));
            __nv_bfloat16 lw = __float2bfloat16(a.w - __bfloat162float(hw));
            __nv_bfloat162* dh = (__nv_bfloat162*)&sAh[r * SA_STR + c4];
            __nv_bfloat162* dl = (__nv_bfloat162*)&sAl[r * SA_STR + c4];
            dh[0] = __nv_bfloat162(hx, hy); dh[1] = __nv_bfloat162(hz, hw);
            dl[0] = __nv_bfloat162(lx, ly); dl[1] = __nv_bfloat162(lz, lw);

            int rB = f >> 5;
            int cB = (f & 31) << 2;
            float4 b = pb[i];
            __nv_bfloat16 bhx = __float2bfloat16(b.x);
            __nv_bfloat16 bhy = __float2bfloat16(b.y);
            __nv_bfloat16 bhz = __float2bfloat16(b.z);
            __nv_bfloat16 bhw = __float2bfloat16(b.w);
            __nv_bfloat16 blx = __float2bfloat16(b.x - __bfloat162float(bhx));
            __nv_bfloat16 bly = __float2bfloat16(b.y - __bfloat162float(bhy));
            __nv_bfloat16 blz = __float2bfloat16(b.z - __bfloat162float(bhz));
            __nv_bfloat16 blw = __float2bfloat16(b.w - __bfloat162float(bhw));
            __nv_bfloat162* eh = (__nv_bfloat162*)&sBh[rB * SB_STR + cB];
            __nv_bfloat162* el = (__nv_bfloat162*)&sBl[rB * SB_STR + cB];
            eh[0] = __nv_bfloat162(bhx, bhy); eh[1] = __nv_bfloat162(bhz, bhw);
            el[0] = __nv_bfloat162(blx, bly); el[1] = __nv_bfloat162(blz, blw);
        }
        __syncthreads();

        // prefetch next chunk while computing
        int kn = k0 + BK;
        if (kn < K) {
            #pragma unroll
            for (int i = 0; i < 4; i++) {
                int f = tid + i * 256;
                int r = f >> 3;
                int c4 = (f & 7) << 2;
                pa[i] = *(const float4*)(A + (size_t)(rowBase + r) * K + kn + c4);
                int rB = f >> 5;
                int cB = (f & 31) << 2;
                pb[i] = *(const float4*)(W + (size_t)(kn + rB) * M + colBase + cB);
            }
        }

        // compute: 2 k-steps of 16
        #pragma unroll
        for (int ks = 0; ks < BK; ks += 16) {
            wmma::fragment<wmma::matrix_a, 16, 16, 16, __nv_bfloat16, wmma::row_major> ah[2], al[2];
            wmma::fragment<wmma::matrix_b, 16, 16, 16, __nv_bfloat16, wmma::row_major> bh[4], bl[4];
            #pragma unroll
            for (int i = 0; i < 2; i++)
                wmma::load_matrix_sync(ah[i], &sAh[(wm * 32 + i * 16) * SA_STR + ks], SA_STR);
            #pragma unroll
            for (int j = 0; j < 4; j++)
                wmma::load_matrix_sync(bh[j], &sBh[ks * SB_STR + wn * 64 + j * 16], SB_STR);
            #pragma unroll
            for (int i = 0; i < 2; i++)
                #pragma unroll
                for (int j = 0; j < 4; j++)
                    wmma::mma_sync(acc[i][j], ah[i], bh[j], acc[i][j]);
            #pragma unroll
            for (int j = 0; j < 4; j++)
                wmma::load_matrix_sync(bl[j], &sBl[ks * SB_STR + wn * 64 + j * 16], SB_STR);
            #pragma unroll
            for (int i = 0; i < 2; i++)
                #pragma unroll
                for (int j = 0; j < 4; j++)
                    wmma::mma_sync(acc[i][j], ah[i], bl[j], acc[i][j]);
            #pragma unroll
            for (int i = 0; i < 2; i++)
                wmma::load_matrix_sync(al[i], &sAl[(wm * 32 + i * 16) * SA_STR + ks], SA_STR);
            #pragma unroll
            for (int i = 0; i < 2; i++)
                #pragma unroll
                for (int j = 0; j < 4; j++)
                    wmma::mma_sync(acc[i][j], al[i], bh[j], acc[i][j]);
        }
        __syncthreads();
    }

    // epilogue: stage accumulators in smem, fuse bias (+ReLU), write fp32
    float* stg = (float*)dynsmem + wid * (32 * EPI_STR);
    #pragma unroll
    for (int i = 0; i < 2; i++)
        #pragma unroll
        for (int j = 0; j < 4; j++)
            wmma::store_matrix_sync(stg + i * 16 * EPI_STR + j * 16, acc[i][j],
                                    EPI_STR, wmma::mem_row_major);
    __syncwarp();

    int rowW = rowBase + wm * 32;
    int colW = colBase + wn * 64;
    #pragma unroll
    for (int it = 0; it < 16; it++) {
        int f = it * 32 + lane;         // 0..511
        int r = f >> 4;                 // 0..31
        int c4 = (f & 15) << 2;         // 0..60
        float4 v = *(float4*)(stg + r * EPI_STR + c4);
        float4 bb = *(const float4*)(bias + colW + c4);
        v.x += bb.x; v.y += bb.y; v.z += bb.z; v.w += bb.w;
        if (RELU) {
            v.x = fmaxf(v.x, 0.f); v.y = fmaxf(v.y, 0.f);
            v.z = fmaxf(v.z, 0.f); v.w = fmaxf(v.w, 0.f);
        }
        *(float4*)(C + (size_t)(rowW + r) * M + colW + c4) = v;
    }
}

// ---------------- flash-style attention (fp32) ----------------
#define ASTR 68
__global__ __launch_bounds__(256)
void attn_kernel(const float* __restrict__ Q, const float* __restrict__ Kk,
                 const float* __restrict__ Vv, const int* __restrict__ mask,
                 float* __restrict__ O) {
    extern __shared__ float sm[];
    float* Qts = sm;
    float* Kts = sm + 64 * ASTR;
    float* Vs  = sm + 2 * 64 * ASTR;
    float* Pts = sm + 3 * 64 * ASTR;

    int tid = threadIdx.x;
    int tx = tid & 15, ty = tid >> 4;
    int bh = blockIdx.y;
    int b  = bh >> 3;
    int hh = bh & 7;
    int q0 = blockIdx.x * 64;
    const float scale = 0.125f;

    #pragma unroll
    for (int i = 0; i < 4; i++) {
        int f4 = tid + i * 256;
        int q  = f4 >> 4;
        int d4 = (f4 & 15) * 4;
        float4 a = *(const float4*)(Q + (size_t)(b * SEQ + q0 + q) * EDIM + hh * HD + d4);
        Qts[(d4 + 0) * ASTR + q] = a.x;
        Qts[(d4 + 1) * ASTR + q] = a.y;
        Qts[(d4 + 2) * ASTR + q] = a.z;
        Qts[(d4 + 3) * ASTR + q] = a.w;
    }

    float accO[4][4] = {};
    float mrun[4] = {-1e30f, -1e30f, -1e30f, -1e30f};
    float lrun[4] = {0.f, 0.f, 0.f, 0.f};

    __syncthreads();

    for (int k0 = 0; k0 < SEQ; k0 += 64) {
        #pragma unroll
        for (int i = 0; i < 4; i++) {
            int f4 = tid + i * 256;
            int k  = f4 >> 4;
            int d4 = (f4 & 15) * 4;
            float4 a = *(const float4*)(Kk + (size_t)(b * SEQ + k0 + k) * EDIM + hh * HD + d4);
            Kts[(d4 + 0) * ASTR + k] = a.x;
            Kts[(d4 + 1) * ASTR + k] = a.y;
            Kts[(d4 + 2) * ASTR + k] = a.z;
            Kts[(d4 + 3) * ASTR + k] = a.w;
            float4 v = *(const float4*)(Vv + (size_t)(b * SEQ + k0 + k) * EDIM + hh * HD + d4);
            *(float4*)&Vs[k * ASTR + d4] = v;
        }
        __syncthreads();

        float s[4][4] = {};
        #pragma unroll 8
        for (int d = 0; d < 64; d++) {
            float4 qa = *(const float4*)&Qts[d * ASTR + ty * 4];
            float4 kb = *(const float4*)&Kts[d * ASTR + tx * 4];
            float av[4] = {qa.x, qa.y, qa.z, qa.w};
            float bv[4] = {kb.x, kb.y, kb.z, kb.w};
            #pragma unroll
            for (int i = 0; i < 4; i++)
                #pragma unroll
                for (int j = 0; j < 4; j++)
                    s[i][j] = fmaf(av[i], bv[j], s[i][j]);
        }

        int4 mk = *(const int4*)(mask + b * SEQ + k0 + tx * 4);
        int mv[4] = {mk.x, mk.y, mk.z, mk.w};
        #pragma unroll
        for (int i = 0; i < 4; i++)
            #pragma unroll
            for (int j = 0; j < 4; j++)
                s[i][j] = (mv[j] == 0) ? -1e20f : s[i][j] * scale;

        #pragma unroll
        for (int i = 0; i < 4; i++) {
            float mloc = fmaxf(fmaxf(s[i][0], s[i][1]), fmaxf(s[i][2], s[i][3]));
            #pragma unroll
            for (int off = 8; off; off >>= 1)
                mloc = fmaxf(mloc, __shfl_xor_sync(0xffffffffu, mloc, off, 16));
            float mnew = fmaxf(mrun[i], mloc);
            float corr = __expf(mrun[i] - mnew);
            float psum = 0.f;
            #pragma unroll
            for (int j = 0; j < 4; j++) {
                float p = __expf(s[i][j] - mnew);
                Pts[(tx * 4 + j) * ASTR + ty * 4 + i] = p;
                psum += p;
            }
            #pragma unroll
            for (int off = 8; off; off >>= 1)
                psum += __shfl_xor_sync(0xffffffffu, psum, off, 16);
            lrun[i] = lrun[i] * corr + psum;
            mrun[i] = mnew;
            #pragma unroll
            for (int j = 0; j < 4; j++)
                accO[i][j] *= corr;
        }
        __syncthreads();

        #pragma unroll 8
        for (int kk = 0; kk < 64; kk++) {
            float4 pa = *(const float4*)&Pts[kk * ASTR + ty * 4];
            float4 vb = *(const float4*)&Vs[kk * ASTR + tx * 4];
            float av[4] = {pa.x, pa.y, pa.z, pa.w};
            float bv[4] = {vb.x, vb.y, vb.z, vb.w};
            #pragma unroll
            for (int i = 0; i < 4; i++)
                #pragma unroll
                for (int j = 0; j < 4; j++)
                    accO[i][j] = fmaf(av[i], bv[j], accO[i][j]);
        }
        __syncthreads();
    }

    #pragma unroll
    for (int i = 0; i < 4; i++) {
        float inv = 1.f / lrun[i];
        float4 o = {accO[i][0] * inv, accO[i][1] * inv, accO[i][2] * inv, accO[i][3] * inv};
        *(float4*)(O + (size_t)(b * SEQ + q0 + ty * 4 + i) * EDIM + hh * HD + tx * 4) = o;
    }
}

// ---------------- residual + LayerNorm ----------------
__global__ __launch_bounds__(128)
void ln_kernel(const float* __restrict__ A, const float* __restrict__ R,
               const float* __restrict__ g, const float* __restrict__ be,
               float* __restrict__ out) {
    __shared__ float red[4];
    int n = blockIdx.x;
    int t = threadIdx.x;
    float4 a = ((const float4*)(A + (size_t)n * EDIM))[t];
    float4 r = ((const float4*)(R + (size_t)n * EDIM))[t];
    float v[4] = {a.x + r.x, a.y + r.y, a.z + r.z, a.w + r.w};

    float s = v[0] + v[1] + v[2] + v[3];
    #pragma unroll
    for (int o = 16; o; o >>= 1) s += __shfl_xor_sync(0xffffffffu, s, o);
    if ((t & 31) == 0) red[t >> 5] = s;
    __syncthreads();
    float mu = (red[0] + red[1] + red[2] + red[3]) * (1.f / EDIM);
    __syncthreads();

    v[0] -= mu; v[1] -= mu; v[2] -= mu; v[3] -= mu;
    float sq = v[0] * v[0] + v[1] * v[1] + v[2] * v[2] + v[3] * v[3];
    #pragma unroll
    for (int o = 16; o; o >>= 1) sq += __shfl_xor_sync(0xffffffffu, sq, o);
    if ((t & 31) == 0) red[t >> 5] = sq;
    __syncthreads();
    float var = (red[0] + red[1] + red[2] + red[3]) * (1.f / EDIM);
    float rs = rsqrtf(var + 1e-6f);

    float4 gg = ((const float4*)g)[t];
    float4 bb = ((const float4*)be)[t];
    float4 o;
    o.x = v[0] * rs * gg.x + bb.x;
    o.y = v[1] * rs * gg.y + bb.y;
    o.z = v[2] * rs * gg.z + bb.z;
    o.w = v[3] * rs * gg.w + bb.w;
    ((float4*)(out + (size_t)n * EDIM))[t] = o;
}

// ---------------- launcher ----------------
extern "C" void kernel_launch(void* const* d_in, const int* in_sizes, int n_in,
                              void* d_out, int out_size) {
    const int*   x    = (const int*)  d_in[0];
    const int*   mask = (const int*)  d_in[1];
    const float* emb  = (const float*)d_in[2];
    const float* pos  = (const float*)d_in[3];
    const float* Wq   = (const float*)d_in[4];
    const float* bq   = (const float*)d_in[5];
    const float* Wk   = (const float*)d_in[6];
    const float* bk   = (const float*)d_in[7];
    const float* Wv   = (const float*)d_in[8];
    const float* bv   = (const float*)d_in[9];
    const float* Wo   = (const float*)d_in[10];
    const float* bo   = (const float*)d_in[11];
    const float* g1   = (const float*)d_in[12];
    const float* be1  = (const float*)d_in[13];
    const float* g2   = (const float*)d_in[14];
    const float* be2  = (const float*)d_in[15];
    const float* W1   = (const float*)d_in[16];
    const float* bf1  = (const float*)d_in[17];
    const float* W2   = (const float*)d_in[18];
    const float* bf2  = (const float*)d_in[19];
    float* outp = (float*)d_out;

    float *h, *q, *k, *v, *a, *p, *f;
    cudaGetSymbolAddress((void**)&h, g_h);
    cudaGetSymbolAddress((void**)&q, g_q);
    cudaGetSymbolAddress((void**)&k, g_k);
    cudaGetSymbolAddress((void**)&v, g_v);
    cudaGetSymbolAddress((void**)&a, g_a);
    cudaGetSymbolAddress((void**)&p, g_p);
    cudaGetSymbolAddress((void**)&f, g_f);

    const int attn_smem = 4 * 64 * ASTR * sizeof(float);
    cudaFuncSetAttribute(attn_kernel, cudaFuncAttributeMaxDynamicSharedMemorySize, attn_smem);
    cudaFuncSetAttribute(gemm_bf16x3_kernel<false>, cudaFuncAttributeMaxDynamicSharedMemorySize, GEMM_SMEM);
    cudaFuncSetAttribute(gemm_bf16x3_kernel<true>,  cudaFuncAttributeMaxDynamicSharedMemorySize, GEMM_SMEM);

    embed_kernel<<<(NTOK * EDIM) / 256, 256>>>(x, emb, pos, h);

    dim3 gE(EDIM / BN, NTOK / BM);    // (4, 64)
    dim3 gF(FFDIM / BN, NTOK / BM);   // (16, 64)

    for (int l = 0; l < NLAYER; l++) {
        const float* wq = Wq + (size_t)l * EDIM * EDIM;
        const float* wk = Wk + (size_t)l * EDIM * EDIM;
        const float* wv = Wv + (size_t)l * EDIM * EDIM;
        const float* wo = Wo + (size_t)l * EDIM * EDIM;
        const float* w1 = W1 + (size_t)l * EDIM * FFDIM;
        const float* w2 = W2 + (size_t)l * FFDIM * EDIM;

        gemm_bf16x3_kernel<false><<<gE, 256, GEMM_SMEM>>>(h, wq, bq + l * EDIM, q, EDIM, EDIM);
        gemm_bf16x3_kernel<false><<<gE, 256, GEMM_SMEM>>>(h, wk, bk + l * EDIM, k, EDIM, EDIM);
        gemm_bf16x3_kernel<false><<<gE, 256, GEMM_SMEM>>>(h, wv, bv + l * EDIM, v, EDIM, EDIM);

        attn_kernel<<<dim3(SEQ / 64, NB * HEADS), 256, attn_smem>>>(q, k, v, mask, a);

        gemm_bf16x3_kernel<false><<<gE, 256, GEMM_SMEM>>>(a, wo, bo + l * EDIM, p, EDIM, EDIM);
        ln_kernel<<<NTOK, 128>>>(p, h, g1 + l * EDIM, be1 + l * EDIM, h);

        gemm_bf16x3_kernel<true><<<gF, 256, GEMM_SMEM>>>(h, w1, bf1 + l * FFDIM, f, EDIM, FFDIM);
        gemm_bf16x3_kernel<false><<<gE, 256, GEMM_SMEM>>>(f, w2, bf2 + l * EDIM, p, FFDIM, EDIM);

        float* lnout = (l == NLAYER - 1) ? outp : h;
        ln_kernel<<<NTOK, 128>>>(p, h, g2 + l * EDIM, be2 + l * EDIM, lnout);
    }
}

// round 3
// speedup vs baseline: 1.7141x; 1.2966x over previous
#include <cuda_runtime.h>
#include <cuda_bf16.h>
#include <mma.h>
#include <math.h>

using namespace nvcuda;

#define NTOK 8192
#define EDIM 512
#define SEQ  2048
#define NB   4
#define HEADS 8
#define HD   64
#define FFDIM 2048
#define NLAYER 2

// ---------------- scratch (device globals; no allocation) ----------------
__device__ float g_h[NTOK * EDIM];
__device__ float g_q[NTOK * EDIM];
__device__ float g_k[NTOK * EDIM];
__device__ float g_v[NTOK * EDIM];
__device__ float g_a[NTOK * EDIM];
__device__ float g_p[NTOK * EDIM];
__device__ float g_f[NTOK * FFDIM];

__device__ __forceinline__ void split2(float x, float y,
                                       __nv_bfloat162& h2, __nv_bfloat162& l2) {
    __nv_bfloat16 hx = __float2bfloat16(x);
    __nv_bfloat16 hy = __float2bfloat16(y);
    h2 = __nv_bfloat162(hx, hy);
    l2 = __nv_bfloat162(__float2bfloat16(x - __bfloat162float(hx)),
                        __float2bfloat16(y - __bfloat162float(hy)));
}

// ---------------- embedding + positional ----------------
__global__ void embed_kernel(const int* __restrict__ x,
                             const float* __restrict__ emb,
                             const float* __restrict__ pos,
                             float* __restrict__ h) {
    int idx = blockIdx.x * blockDim.x + threadIdx.x;
    int n = idx >> 9;
    int e = idx & 511;
    int tok = x[n] + 1;
    int s = n & (SEQ - 1);
    h[idx] = emb[tok * EDIM + e] + pos[s * EDIM + e];
}

// ---------------- bf16x3 tensor-core GEMM ----------------
#define BM 128
#define BN 128
#define BK 32
#define SA_STR 40
#define SB_STR 136
#define EPI_STR 68
#define GEMM_SMEM (8 * 32 * EPI_STR * 4)

template <bool RELU>
__global__ __launch_bounds__(256, 1)
void gemm_bf16x3_kernel(const float* __restrict__ A, const float* __restrict__ W,
                        const float* __restrict__ bias, float* __restrict__ C,
                        int K, int M) {
    extern __shared__ char dynsmem[];
    __nv_bfloat16* sAh = (__nv_bfloat16*)dynsmem;
    __nv_bfloat16* sAl = sAh + BM * SA_STR;
    __nv_bfloat16* sBh = sAl + BM * SA_STR;
    __nv_bfloat16* sBl = sBh + BK * SB_STR;

    int tid = threadIdx.x;
    int lane = tid & 31;
    int wid = tid >> 5;
    int wm = wid & 3;
    int wn = wid >> 2;
    int rowBase = blockIdx.y * BM;
    int colBase = blockIdx.x * BN;

    wmma::fragment<wmma::accumulator, 16, 16, 16, float> acc[2][4];
    #pragma unroll
    for (int i = 0; i < 2; i++)
        #pragma unroll
        for (int j = 0; j < 4; j++)
            wmma::fill_fragment(acc[i][j], 0.0f);

    float4 pa[4], pb[4];
    #pragma unroll
    for (int i = 0; i < 4; i++) {
        int f = tid + i * 256;
        int r = f >> 3;
        int c4 = (f & 7) << 2;
        pa[i] = *(const float4*)(A + (size_t)(rowBase + r) * K + c4);
        int rB = f >> 5;
        int cB = (f & 31) << 2;
        pb[i] = *(const float4*)(W + (size_t)rB * M + colBase + cB);
    }

    for (int k0 = 0; k0 < K; k0 += BK) {
        #pragma unroll
        for (int i = 0; i < 4; i++) {
            int f = tid + i * 256;
            int r = f >> 3;
            int c4 = (f & 7) << 2;
            float4 a = pa[i];
            __nv_bfloat162 h0, l0, h1, l1;
            split2(a.x, a.y, h0, l0);
            split2(a.z, a.w, h1, l1);
            __nv_bfloat162* dh = (__nv_bfloat162*)&sAh[r * SA_STR + c4];
            __nv_bfloat162* dl = (__nv_bfloat162*)&sAl[r * SA_STR + c4];
            dh[0] = h0; dh[1] = h1;
            dl[0] = l0; dl[1] = l1;

            int rB = f >> 5;
            int cB = (f & 31) << 2;
            float4 b = pb[i];
            split2(b.x, b.y, h0, l0);
            split2(b.z, b.w, h1, l1);
            __nv_bfloat162* eh = (__nv_bfloat162*)&sBh[rB * SB_STR + cB];
            __nv_bfloat162* el = (__nv_bfloat162*)&sBl[rB * SB_STR + cB];
            eh[0] = h0; eh[1] = h1;
            el[0] = l0; el[1] = l1;
        }
        __syncthreads();

        int kn = k0 + BK;
        if (kn < K) {
            #pragma unroll
            for (int i = 0; i < 4; i++) {
                int f = tid + i * 256;
                int r = f >> 3;
                int c4 = (f & 7) << 2;
                pa[i] = *(const float4*)(A + (size_t)(rowBase + r) * K + kn + c4);
                int rB = f >> 5;
                int cB = (f & 31) << 2;
                pb[i] = *(const float4*)(W + (size_t)(kn + rB) * M + colBase + cB);
            }
        }

        #pragma unroll
        for (int ks = 0; ks < BK; ks += 16) {
            wmma::fragment<wmma::matrix_a, 16, 16, 16, __nv_bfloat16, wmma::row_major> ah[2], al[2];
            wmma::fragment<wmma::matrix_b, 16, 16, 16, __nv_bfloat16, wmma::row_major> bh[4], bl[4];
            #pragma unroll
            for (int i = 0; i < 2; i++)
                wmma::load_matrix_sync(ah[i], &sAh[(wm * 32 + i * 16) * SA_STR + ks], SA_STR);
            #pragma unroll
            for (int j = 0; j < 4; j++)
                wmma::load_matrix_sync(bh[j], &sBh[ks * SB_STR + wn * 64 + j * 16], SB_STR);
            #pragma unroll
            for (int i = 0; i < 2; i++)
                #pragma unroll
                for (int j = 0; j < 4; j++)
                    wmma::mma_sync(acc[i][j], ah[i], bh[j], acc[i][j]);
            #pragma unroll
            for (int j = 0; j < 4; j++)
                wmma::load_matrix_sync(bl[j], &sBl[ks * SB_STR + wn * 64 + j * 16], SB_STR);
            #pragma unroll
            for (int i = 0; i < 2; i++)
                #pragma unroll
                for (int j = 0; j < 4; j++)
                    wmma::mma_sync(acc[i][j], ah[i], bl[j], acc[i][j]);
            #pragma unroll
            for (int i = 0; i < 2; i++)
                wmma::load_matrix_sync(al[i], &sAl[(wm * 32 + i * 16) * SA_STR + ks], SA_STR);
            #pragma unroll
            for (int i = 0; i < 2; i++)
                #pragma unroll
                for (int j = 0; j < 4; j++)
                    wmma::mma_sync(acc[i][j], al[i], bh[j], acc[i][j]);
        }
        __syncthreads();
    }

    float* stg = (float*)dynsmem + wid * (32 * EPI_STR);
    #pragma unroll
    for (int i = 0; i < 2; i++)
        #pragma unroll
        for (int j = 0; j < 4; j++)
            wmma::store_matrix_sync(stg + i * 16 * EPI_STR + j * 16, acc[i][j],
                                    EPI_STR, wmma::mem_row_major);
    __syncwarp();

    int rowW = rowBase + wm * 32;
    int colW = colBase + wn * 64;
    #pragma unroll
    for (int it = 0; it < 16; it++) {
        int f = it * 32 + lane;
        int r = f >> 4;
        int c4 = (f & 15) << 2;
        float4 v = *(float4*)(stg + r * EPI_STR + c4);
        float4 bb = *(const float4*)(bias + colW + c4);
        v.x += bb.x; v.y += bb.y; v.z += bb.z; v.w += bb.w;
        if (RELU) {
            v.x = fmaxf(v.x, 0.f); v.y = fmaxf(v.y, 0.f);
            v.z = fmaxf(v.z, 0.f); v.w = fmaxf(v.w, 0.f);
        }
        *(float4*)(C + (size_t)(rowW + r) * M + colW + c4) = v;
    }
}

// ---------------- tensor-core flash attention (bf16x3) ----------------
// CTA: 64-query tile, stream 64-key blocks, 256 threads / 8 warps.
// Warp tile: 16 rows x 32 cols of the 64x64 S / O-part tiles.
#define KSTR 72          // bf16 smem stride
#define SSTR 68          // fp32 smem stride
#define AQH 0
#define AQL (64 * KSTR)
#define AKH (2 * 64 * KSTR)
#define AKL (3 * 64 * KSTR)
#define AVH (4 * 64 * KSTR)
#define AVL (5 * 64 * KSTR)
#define APH (6 * 64 * KSTR)
#define APL (7 * 64 * KSTR)
#define ATTN_SMEM (8 * 64 * KSTR * 2 + 64 * SSTR * 4)   // 73728 + 17408 = 91136

__global__ __launch_bounds__(256, 2)
void attn_tc_kernel(const float* __restrict__ Qg, const float* __restrict__ Kg,
                    const float* __restrict__ Vg, const int* __restrict__ mask,
                    float* __restrict__ Og) {
    extern __shared__ char smraw[];
    __nv_bfloat16* sb = (__nv_bfloat16*)smraw;
    float* Sf = (float*)(smraw + 8 * 64 * KSTR * 2);

    int tid = threadIdx.x;
    int wid = tid >> 5;
    int wr = (wid & 3) * 16;          // warp row base within tile
    int wc = (wid >> 2) * 32;         // warp col base within tile
    int b  = blockIdx.y >> 3;
    int hh = blockIdx.y & 7;
    int q0 = blockIdx.x * 64;

    const float* qbase = Qg + (size_t)(b * SEQ + q0) * EDIM + hh * HD;
    const float* kbase = Kg + (size_t)(b * SEQ) * EDIM + hh * HD;
    const float* vbase = Vg + (size_t)(b * SEQ) * EDIM + hh * HD;

    // load Q tile (scaled by 1/8), split to hi/lo
    #pragma unroll
    for (int i = 0; i < 4; i++) {
        int f = tid + i * 256;
        int r = f >> 4;
        int d4 = (f & 15) << 2;
        float4 a = *(const float4*)(qbase + (size_t)r * EDIM + d4);
        a.x *= 0.125f; a.y *= 0.125f; a.z *= 0.125f; a.w *= 0.125f;
        __nv_bfloat162 h0, l0, h1, l1;
        split2(a.x, a.y, h0, l0);
        split2(a.z, a.w, h1, l1);
        __nv_bfloat162* dh = (__nv_bfloat162*)&sb[AQH + r * KSTR + d4];
        __nv_bfloat162* dl = (__nv_bfloat162*)&sb[AQL + r * KSTR + d4];
        dh[0] = h0; dh[1] = h1;
        dl[0] = l0; dl[1] = l1;
    }

    int rr = tid >> 2;               // row owned for softmax / O accum
    int pp = tid & 3;                // 16-col segment
    float o_acc[16];
    #pragma unroll
    for (int i = 0; i < 16; i++) o_acc[i] = 0.f;
    float mrun = -1e30f, lrun = 0.f;

    // prefetch K/V block 0
    float4 pk[4], pv[4];
    #pragma unroll
    for (int i = 0; i < 4; i++) {
        int f = tid + i * 256;
        int r = f >> 4;
        int d4 = (f & 15) << 2;
        pk[i] = *(const float4*)(kbase + (size_t)r * EDIM + d4);
        pv[i] = *(const float4*)(vbase + (size_t)r * EDIM + d4);
    }

    for (int kb = 0; kb < SEQ / 64; kb++) {
        // stage K/V into smem (hi/lo)
        #pragma unroll
        for (int i = 0; i < 4; i++) {
            int f = tid + i * 256;
            int r = f >> 4;
            int d4 = (f & 15) << 2;
            __nv_bfloat162 h0, l0, h1, l1;
            split2(pk[i].x, pk[i].y, h0, l0);
            split2(pk[i].z, pk[i].w, h1, l1);
            __nv_bfloat162* dh = (__nv_bfloat162*)&sb[AKH + r * KSTR + d4];
            __nv_bfloat162* dl = (__nv_bfloat162*)&sb[AKL + r * KSTR + d4];
            dh[0] = h0; dh[1] = h1; dl[0] = l0; dl[1] = l1;
            split2(pv[i].x, pv[i].y, h0, l0);
            split2(pv[i].z, pv[i].w, h1, l1);
            dh = (__nv_bfloat162*)&sb[AVH + r * KSTR + d4];
            dl = (__nv_bfloat162*)&sb[AVL + r * KSTR + d4];
            dh[0] = h0; dh[1] = h1; dl[0] = l0; dl[1] = l1;
        }
        __syncthreads();

        // prefetch next block
        if (kb + 1 < SEQ / 64) {
            #pragma unroll
            for (int i = 0; i < 4; i++) {
                int f = tid + i * 256;
                int r = (kb + 1) * 64 + (f >> 4);
                int d4 = (f & 15) << 2;
                pk[i] = *(const float4*)(kbase + (size_t)r * EDIM + d4);
                pv[i] = *(const float4*)(vbase + (size_t)r * EDIM + d4);
            }
        }

        // S = Q @ K^T (bf16x3)
        {
            wmma::fragment<wmma::matrix_a, 16, 16, 16, __nv_bfloat16, wmma::row_major> qa_h, qa_l;
            wmma::fragment<wmma::matrix_b, 16, 16, 16, __nv_bfloat16, wmma::col_major> kb_h[2], kb_l[2];
            wmma::fragment<wmma::accumulator, 16, 16, 16, float> sacc[2];
            wmma::fill_fragment(sacc[0], 0.f);
            wmma::fill_fragment(sacc[1], 0.f);
            #pragma unroll
            for (int kk = 0; kk < 4; kk++) {
                wmma::load_matrix_sync(qa_h, &sb[AQH + wr * KSTR + kk * 16], KSTR);
                wmma::load_matrix_sync(qa_l, &sb[AQL + wr * KSTR + kk * 16], KSTR);
                #pragma unroll
                for (int j = 0; j < 2; j++) {
                    wmma::load_matrix_sync(kb_h[j], &sb[AKH + (wc + j * 16) * KSTR + kk * 16], KSTR);
                    wmma::load_matrix_sync(kb_l[j], &sb[AKL + (wc + j * 16) * KSTR + kk * 16], KSTR);
                }
                #pragma unroll
                for (int j = 0; j < 2; j++) {
                    wmma::mma_sync(sacc[j], qa_h, kb_h[j], sacc[j]);
                    wmma::mma_sync(sacc[j], qa_h, kb_l[j], sacc[j]);
                    wmma::mma_sync(sacc[j], qa_l, kb_h[j], sacc[j]);
                }
            }
            #pragma unroll
            for (int j = 0; j < 2; j++)
                wmma::store_matrix_sync(&Sf[wr * SSTR + wc + j * 16], sacc[j], SSTR, wmma::mem_row_major);
        }
        __syncthreads();

        // softmax (4 threads per row), write P hi/lo
        {
            const float* srow = &Sf[rr * SSTR + pp * 16];
            const int4* mrow = (const int4*)(mask + b * SEQ + kb * 64 + pp * 16);
            float s[16];
            #pragma unroll
            for (int i = 0; i < 4; i++) {
                float4 sv = *(const float4*)(srow + i * 4);
                int4 mk = mrow[i];
                s[4 * i + 0] = mk.x ? sv.x : -1e20f;
                s[4 * i + 1] = mk.y ? sv.y : -1e20f;
                s[4 * i + 2] = mk.z ? sv.z : -1e20f;
                s[4 * i + 3] = mk.w ? sv.w : -1e20f;
            }
            float mloc = s[0];
            #pragma unroll
            for (int i = 1; i < 16; i++) mloc = fmaxf(mloc, s[i]);
            mloc = fmaxf(mloc, __shfl_xor_sync(0xffffffffu, mloc, 1));
            mloc = fmaxf(mloc, __shfl_xor_sync(0xffffffffu, mloc, 2));
            float mnew = fmaxf(mrun, mloc);
            float corr = __expf(mrun - mnew);
            mrun = mnew;
            float psum = 0.f;
            __nv_bfloat162* ph = (__nv_bfloat162*)&sb[APH + rr * KSTR + pp * 16];
            __nv_bfloat162* pl = (__nv_bfloat162*)&sb[APL + rr * KSTR + pp * 16];
            #pragma unroll
            for (int i = 0; i < 8; i++) {
                float p0 = __expf(s[2 * i] - mnew);
                float p1 = __expf(s[2 * i + 1] - mnew);
                psum += p0 + p1;
                __nv_bfloat162 h2, l2;
                split2(p0, p1, h2, l2);
                ph[i] = h2;
                pl[i] = l2;
            }
            psum += __shfl_xor_sync(0xffffffffu, psum, 1);
            psum += __shfl_xor_sync(0xffffffffu, psum, 2);
            lrun = lrun * corr + psum;
            #pragma unroll
            for (int i = 0; i < 16; i++) o_acc[i] *= corr;
        }
        __syncthreads();

        // Opart = P @ V (bf16x3)
        {
            wmma::fragment<wmma::matrix_a, 16, 16, 16, __nv_bfloat16, wmma::row_major> pa_h, pa_l;
            wmma::fragment<wmma::matrix_b, 16, 16, 16, __nv_bfloat16, wmma::row_major> vb_h[2], vb_l[2];
            wmma::fragment<wmma::accumulator, 16, 16, 16, float> oacc[2];
            wmma::fill_fragment(oacc[0], 0.f);
            wmma::fill_fragment(oacc[1], 0.f);
            #pragma unroll
            for (int kk = 0; kk < 4; kk++) {
                wmma::load_matrix_sync(pa_h, &sb[APH + wr * KSTR + kk * 16], KSTR);
                wmma::load_matrix_sync(pa_l, &sb[APL + wr * KSTR + kk * 16], KSTR);
                #pragma unroll
                for (int j = 0; j < 2; j++) {
                    wmma::load_matrix_sync(vb_h[j], &sb[AVH + (kk * 16) * KSTR + wc + j * 16], KSTR);
                    wmma::load_matrix_sync(vb_l[j], &sb[AVL + (kk * 16) * KSTR + wc + j * 16], KSTR);
                }
                #pragma unroll
                for (int j = 0; j < 2; j++) {
                    wmma::mma_sync(oacc[j], pa_h, vb_h[j], oacc[j]);
                    wmma::mma_sync(oacc[j], pa_h, vb_l[j], oacc[j]);
                    wmma::mma_sync(oacc[j], pa_l, vb_h[j], oacc[j]);
                }
            }
            #pragma unroll
            for (int j = 0; j < 2; j++)
                wmma::store_matrix_sync(&Sf[wr * SSTR + wc + j * 16], oacc[j], SSTR, wmma::mem_row_major);
        }
        __syncthreads();

        // accumulate O part
        {
            const float* orow = &Sf[rr * SSTR + pp * 16];
            #pragma unroll
            for (int i = 0; i < 4; i++) {
                float4 op = *(const float4*)(orow + i * 4);
                o_acc[4 * i + 0] += op.x;
                o_acc[4 * i + 1] += op.y;
                o_acc[4 * i + 2] += op.z;
                o_acc[4 * i + 3] += op.w;
            }
        }
    }

    float inv = 1.f / lrun;
    float* obase = Og + (size_t)(b * SEQ + q0 + rr) * EDIM + hh * HD + pp * 16;
    #pragma unroll
    for (int i = 0; i < 4; i++) {
        float4 o = {o_acc[4 * i + 0] * inv, o_acc[4 * i + 1] * inv,
                    o_acc[4 * i + 2] * inv, o_acc[4 * i + 3] * inv};
        *(float4*)(obase + i * 4) = o;
    }
}

// ---------------- residual + LayerNorm ----------------
__global__ __launch_bounds__(128)
void ln_kernel(const float* __restrict__ A, const float* __restrict__ R,
               const float* __restrict__ g, const float* __restrict__ be,
               float* __restrict__ out) {
    __shared__ float red[4];
    int n = blockIdx.x;
    int t = threadIdx.x;
    float4 a = ((const float4*)(A + (size_t)n * EDIM))[t];
    float4 r = ((const float4*)(R + (size_t)n * EDIM))[t];
    float v[4] = {a.x + r.x, a.y + r.y, a.z + r.z, a.w + r.w};

    float s = v[0] + v[1] + v[2] + v[3];
    #pragma unroll
    for (int o = 16; o; o >>= 1) s += __shfl_xor_sync(0xffffffffu, s, o);
    if ((t & 31) == 0) red[t >> 5] = s;
    __syncthreads();
    float mu = (red[0] + red[1] + red[2] + red[3]) * (1.f / EDIM);
    __syncthreads();

    v[0] -= mu; v[1] -= mu; v[2] -= mu; v[3] -= mu;
    float sq = v[0] * v[0] + v[1] * v[1] + v[2] * v[2] + v[3] * v[3];
    #pragma unroll
    for (int o = 16; o; o >>= 1) sq += __shfl_xor_sync(0xffffffffu, sq, o);
    if ((t & 31) == 0) red[t >> 5] = sq;
    __syncthreads();
    float var = (red[0] + red[1] + red[2] + red[3]) * (1.f / EDIM);
    float rs = rsqrtf(var + 1e-6f);

    float4 gg = ((const float4*)g)[t];
    float4 bb = ((const float4*)be)[t];
    float4 o;
    o.x = v[0] * rs * gg.x + bb.x;
    o.y = v[1] * rs * gg.y + bb.y;
    o.z = v[2] * rs * gg.z + bb.z;
    o.w = v[3] * rs * gg.w + bb.w;
    ((float4*)(out + (size_t)n * EDIM))[t] = o;
}

// ---------------- launcher ----------------
extern "C" void kernel_launch(void* const* d_in, const int* in_sizes, int n_in,
                              void* d_out, int out_size) {
    const int*   x    = (const int*)  d_in[0];
    const int*   mask = (const int*)  d_in[1];
    const float* emb  = (const float*)d_in[2];
    const float* pos  = (const float*)d_in[3];
    const float* Wq   = (const float*)d_in[4];
    const float* bq   = (const float*)d_in[5];
    const float* Wk   = (const float*)d_in[6];
    const float* bk   = (const float*)d_in[7];
    const float* Wv   = (const float*)d_in[8];
    const float* bv   = (const float*)d_in[9];
    const float* Wo   = (const float*)d_in[10];
    const float* bo   = (const float*)d_in[11];
    const float* g1   = (const float*)d_in[12];
    const float* be1  = (const float*)d_in[13];
    const float* g2   = (const float*)d_in[14];
    const float* be2  = (const float*)d_in[15];
    const float* W1   = (const float*)d_in[16];
    const float* bf1  = (const float*)d_in[17];
    const float* W2   = (const float*)d_in[18];
    const float* bf2  = (const float*)d_in[19];
    float* outp = (float*)d_out;

    float *h, *q, *k, *v, *a, *p, *f;
    cudaGetSymbolAddress((void**)&h, g_h);
    cudaGetSymbolAddress((void**)&q, g_q);
    cudaGetSymbolAddress((void**)&k, g_k);
    cudaGetSymbolAddress((void**)&v, g_v);
    cudaGetSymbolAddress((void**)&a, g_a);
    cudaGetSymbolAddress((void**)&p, g_p);
    cudaGetSymbolAddress((void**)&f, g_f);

    cudaFuncSetAttribute(attn_tc_kernel, cudaFuncAttributeMaxDynamicSharedMemorySize, ATTN_SMEM);
    cudaFuncSetAttribute(gemm_bf16x3_kernel<false>, cudaFuncAttributeMaxDynamicSharedMemorySize, GEMM_SMEM);
    cudaFuncSetAttribute(gemm_bf16x3_kernel<true>,  cudaFuncAttributeMaxDynamicSharedMemorySize, GEMM_SMEM);

    embed_kernel<<<(NTOK * EDIM) / 256, 256>>>(x, emb, pos, h);

    dim3 gE(EDIM / BN, NTOK / BM);
    dim3 gF(FFDIM / BN, NTOK / BM);

    for (int l = 0; l < NLAYER; l++) {
        const float* wq = Wq + (size_t)l * EDIM * EDIM;
        const float* wk = Wk + (size_t)l * EDIM * EDIM;
        const float* wv = Wv + (size_t)l * EDIM * EDIM;
        const float* wo = Wo + (size_t)l * EDIM * EDIM;
        const float* w1 = W1 + (size_t)l * EDIM * FFDIM;
        const float* w2 = W2 + (size_t)l * FFDIM * EDIM;

        gemm_bf16x3_kernel<false><<<gE, 256, GEMM_SMEM>>>(h, wq, bq + l * EDIM, q, EDIM, EDIM);
        gemm_bf16x3_kernel<false><<<gE, 256, GEMM_SMEM>>>(h, wk, bk + l * EDIM, k, EDIM, EDIM);
        gemm_bf16x3_kernel<false><<<gE, 256, GEMM_SMEM>>>(h, wv, bv + l * EDIM, v, EDIM, EDIM);

        attn_tc_kernel<<<dim3(SEQ / 64, NB * HEADS), 256, ATTN_SMEM>>>(q, k, v, mask, a);

        gemm_bf16x3_kernel<false><<<gE, 256, GEMM_SMEM>>>(a, wo, bo + l * EDIM, p, EDIM, EDIM);
        ln_kernel<<<NTOK, 128>>>(p, h, g1 + l * EDIM, be1 + l * EDIM, h);

        gemm_bf16x3_kernel<true><<<gF, 256, GEMM_SMEM>>>(h, w1, bf1 + l * FFDIM, f, EDIM, FFDIM);
        gemm_bf16x3_kernel<false><<<gE, 256, GEMM_SMEM>>>(f, w2, bf2 + l * EDIM, p, FFDIM, EDIM);

        float* lnout = (l == NLAYER - 1) ? outp : h;
        ln_kernel<<<NTOK, 128>>>(p, h, g2 + l * EDIM, be2 + l * EDIM, lnout);
    }
}